// round 14
// baseline (speedup 1.0000x reference)
#include <cuda_runtime.h>
#include <math.h>

#define N_MAX   32768
#define EMAX    600000
#define FULL_M  0xffffffffu
#define NEG_SLOPE 0.2f
#define EPS_    1e-16f

// ---------------- device scratch (static: no allocation allowed) ----------------
__device__ int   g_counts[N_MAX];
__device__ int   g_rowptr[N_MAX + 1];
__device__ int   g_edge_off[EMAX];
__device__ int   g_csr_src[EMAX];
__device__ __align__(16) float g_h1[N_MAX * 128];
__device__ __align__(16) float g_act1[N_MAX * 128];
__device__ __align__(16) float g_h2[N_MAX * 128];
__device__ float4 g_as[N_MAX];   // per-row alpha_src partials by 32-col chunk
__device__ float4 g_ad[N_MAX];   // per-row alpha_dst partials by 32-col chunk

__device__ __forceinline__ float lrelu(float v) { return v > 0.f ? v : NEG_SLOPE * v; }

// ---------------- CSR construction ----------------
__global__ void zero_kernel(int n) {            // (kernel, not memset: shifts ncu -s 5 onto agg1)
    int i = blockIdx.x * blockDim.x + threadIdx.x;
    if (i < n) g_counts[i] = 0;
}

__global__ void hist_kernel(const int* __restrict__ dst, int E) {
    int i = (blockIdx.x * blockDim.x + threadIdx.x) * 4;
    if (i + 3 < E) {
        int4 d = *(const int4*)(dst + i);
        int o0 = atomicAdd(&g_counts[d.x], 1);
        int o1 = atomicAdd(&g_counts[d.y], 1);
        int o2 = atomicAdd(&g_counts[d.z], 1);
        int o3 = atomicAdd(&g_counts[d.w], 1);
        *(int4*)(g_edge_off + i) = make_int4(o0, o1, o2, o3);
    } else {
        for (int j = i; j < E; j++)
            g_edge_off[j] = atomicAdd(&g_counts[dst[j]], 1);
    }
}

__global__ __launch_bounds__(1024) void scan_kernel(int n) {
    __shared__ int wsum[32];
    int tid = threadIdx.x, lane = tid & 31, wid = tid >> 5;
    int base = tid * 32;
    int local[32];
    int sum = 0;
    #pragma unroll
    for (int j = 0; j < 32; j++) {
        int i = base + j;
        local[j] = sum;
        sum += (i < n) ? (g_counts[i] + 1) : 0;   // +1 = self loop
    }
    int x = sum;
    #pragma unroll
    for (int d = 1; d < 32; d <<= 1) {
        int t = __shfl_up_sync(FULL_M, x, d);
        if (lane >= d) x += t;
    }
    if (lane == 31) wsum[wid] = x;
    __syncthreads();
    if (wid == 0) {
        int y = wsum[lane];
        #pragma unroll
        for (int d = 1; d < 32; d <<= 1) {
            int t = __shfl_up_sync(FULL_M, y, d);
            if (lane >= d) y += t;
        }
        wsum[lane] = y;
    }
    __syncthreads();
    int offset = (x - sum) + (wid > 0 ? wsum[wid - 1] : 0);
    if (tid == 0) g_rowptr[0] = 0;
    #pragma unroll
    for (int j = 0; j < 32; j++) {
        int i = base + j;
        if (i < n) {
            int c = g_counts[i];
            int start = offset + local[j];
            g_rowptr[i + 1] = start + c + 1;
            g_csr_src[start] = i;                 // self loop first
        }
    }
}

__global__ void scatter_kernel(const int* __restrict__ src,
                               const int* __restrict__ dst, int E) {
    int i = (blockIdx.x * blockDim.x + threadIdx.x) * 4;
    if (i + 3 < E) {
        int4 s = *(const int4*)(src + i);
        int4 d = *(const int4*)(dst + i);
        int4 o = *(const int4*)(g_edge_off + i);
        g_csr_src[g_rowptr[d.x] + 1 + o.x] = s.x;
        g_csr_src[g_rowptr[d.y] + 1 + o.y] = s.y;
        g_csr_src[g_rowptr[d.z] + 1 + o.z] = s.z;
        g_csr_src[g_rowptr[d.w] + 1 + o.w] = s.w;
    } else {
        for (int j = i; j < E; j++)
            g_csr_src[g_rowptr[dst[j]] + 1 + g_edge_off[j]] = src[j];
    }
}

// ---------------- GEMM + fused alpha (R13) ----------------
__global__ __launch_bounds__(128) void gemm_alpha(
    const float* __restrict__ A, const float* __restrict__ B,
    float* __restrict__ C, int M,
    const float* __restrict__ av, const float* __restrict__ dv,
    float4* __restrict__ as_out, float4* __restrict__ ad_out)
{
    __shared__ __align__(16) float As[32][68];   // [k][m]
    __shared__ __align__(16) float Bs[32][68];   // [k][n]
    int tid = threadIdx.x;
    int tx = tid & 15, ty = tid >> 4;
    int m0 = blockIdx.x * 64, n0 = blockIdx.y * 64;
    float acc[8][4] = {};
    for (int kk = 0; kk < 4; kk++) {
        int k0 = kk * 32;
        #pragma unroll
        for (int t = 0; t < 4; t++) {
            int idx = tid + t * 128;
            int r = idx >> 3, c4 = idx & 7;
            float4 v = make_float4(0.f, 0.f, 0.f, 0.f);
            int row = m0 + r;
            if (row < M) v = *(const float4*)(A + row * 128 + k0 + c4 * 4);
            As[c4 * 4 + 0][r] = v.x; As[c4 * 4 + 1][r] = v.y;
            As[c4 * 4 + 2][r] = v.z; As[c4 * 4 + 3][r] = v.w;
        }
        #pragma unroll
        for (int t = 0; t < 4; t++) {
            int idx = tid + t * 128;
            int k = idx >> 4, c4 = idx & 15;
            float4 v = *(const float4*)(B + (k0 + k) * 128 + n0 + c4 * 4);
            *(float4*)&Bs[k][c4 * 4] = v;
        }
        __syncthreads();
        #pragma unroll
        for (int k = 0; k < 32; k++) {
            float a[8], b[4];
            *(float4*)&a[0] = *(const float4*)&As[k][ty * 8];
            *(float4*)&a[4] = *(const float4*)&As[k][ty * 8 + 4];
            *(float4*)&b[0] = *(const float4*)&Bs[k][tx * 4];
            #pragma unroll
            for (int i = 0; i < 8; i++)
                #pragma unroll
                for (int j = 0; j < 4; j++)
                    acc[i][j] += a[i] * b[j];
        }
        __syncthreads();
    }
    #pragma unroll
    for (int i = 0; i < 8; i++) {
        int row = m0 + ty * 8 + i;
        if (row < M)
            *(float4*)(C + (size_t)row * 128 + n0 + tx * 4) =
                make_float4(acc[i][0], acc[i][1], acc[i][2], acc[i][3]);
    }
    float a0 = av[n0 + tx * 4], a1 = av[n0 + tx * 4 + 1],
          a2 = av[n0 + tx * 4 + 2], a3 = av[n0 + tx * 4 + 3];
    float d0 = dv[n0 + tx * 4], d1 = dv[n0 + tx * 4 + 1],
          d2 = dv[n0 + tx * 4 + 2], d3 = dv[n0 + tx * 4 + 3];
    int comp = (n0 >> 5) + (tx >> 3);
    #pragma unroll
    for (int i = 0; i < 8; i++) {
        float s = acc[i][0] * a0 + acc[i][1] * a1 + acc[i][2] * a2 + acc[i][3] * a3;
        float d = acc[i][0] * d0 + acc[i][1] * d1 + acc[i][2] * d2 + acc[i][3] * d3;
        s += __shfl_xor_sync(FULL_M, s, 1); d += __shfl_xor_sync(FULL_M, d, 1);
        s += __shfl_xor_sync(FULL_M, s, 2); d += __shfl_xor_sync(FULL_M, d, 2);
        s += __shfl_xor_sync(FULL_M, s, 4); d += __shfl_xor_sync(FULL_M, d, 4);
        int row = m0 + ty * 8 + i;
        if ((tx & 7) == 0 && row < M) {
            ((float*)&as_out[row])[comp] = s;
            ((float*)&ad_out[row])[comp] = d;
        }
    }
}

// ---------------- layer-1 aggregation: 4 warps per node (one head each).
// Per edge: 2 SHFL + 1 coalesced LDG + 1 FMA. Inner idiom unchanged. ----------------
__global__ __launch_bounds__(256) void agg1_kernel(const float* __restrict__ h,
                                                   const float* __restrict__ b1,
                                                   float* __restrict__ out, int n) {
    int gw = (blockIdx.x * blockDim.x + threadIdx.x) >> 5;
    int lane = threadIdx.x & 31;
    int w = gw >> 2, head = gw & 3;          // 4 warps of a node share the block
    if (w >= n) return;
    int beg = g_rowptr[w], end = g_rowptr[w + 1];
    float4 adv = g_ad[w];
    float adh = head == 0 ? adv.x : (head == 1 ? adv.y : (head == 2 ? adv.z : adv.w));
    int coff = head * 32 + lane;

    float acc = 0.f, dn = 0.f;
    for (int g = beg; g < end; g += 32) {
        int i = g + lane;
        float e = 0.f; int s = 0;
        if (i < end) {
            s = g_csr_src[i];
            float4 a = g_as[s];
            float ah = head == 0 ? a.x : (head == 1 ? a.y : (head == 2 ? a.z : a.w));
            e = __expf(lrelu(ah + adh));
        }
        dn += e;
        #pragma unroll
        for (int j = 0; j < 32; j++) {
            float f = __shfl_sync(FULL_M, e, j);
            int  sj = __shfl_sync(FULL_M, s, j);
            if (f > 0.f)
                acc += f * h[(size_t)sj * 128 + coff];
        }
    }
    #pragma unroll
    for (int o = 16; o; o >>= 1)
        dn += __shfl_xor_sync(FULL_M, dn, o);
    float v = acc / (dn + EPS_) + b1[coff];
    out[(size_t)w * 128 + coff] = v > 0.f ? v : expm1f(v);   // ELU(alpha=1)
}

// ---------------- layer-2 aggregation: 4 warps per node (32 channels each) --------
__global__ __launch_bounds__(256) void agg2_kernel(const float* __restrict__ h,
                                                   const float* __restrict__ b2,
                                                   float* __restrict__ out, int n) {
    int gw = (blockIdx.x * blockDim.x + threadIdx.x) >> 5;
    int lane = threadIdx.x & 31;
    int w = gw >> 2, chunk = gw & 3;
    if (w >= n) return;
    int beg = g_rowptr[w], end = g_rowptr[w + 1];
    float4 adv = g_ad[w];
    float adn = (adv.x + adv.y) + (adv.z + adv.w);
    int coff = chunk * 32 + lane;

    float acc = 0.f, dn = 0.f;
    for (int g = beg; g < end; g += 32) {
        int i = g + lane;
        float e = 0.f; int s = 0;
        if (i < end) {
            s = g_csr_src[i];
            float4 a = g_as[s];
            e = __expf(lrelu((a.x + a.y) + (a.z + a.w) + adn));
        }
        dn += e;
        #pragma unroll
        for (int j = 0; j < 32; j++) {
            float f = __shfl_sync(FULL_M, e, j);
            int  sj = __shfl_sync(FULL_M, s, j);
            if (f > 0.f)
                acc += f * h[(size_t)sj * 128 + coff];
        }
    }
    #pragma unroll
    for (int o = 16; o; o >>= 1)
        dn += __shfl_xor_sync(FULL_M, dn, o);
    out[(size_t)w * 128 + coff] = acc / (dn + EPS_) + b2[coff];
}

// ---------------- launch (fork-join: CSR build overlaps GEMM1) ----------------
extern "C" void kernel_launch(void* const* d_in, const int* in_sizes, int n_in,
                              void* d_out, int out_size) {
    const float* x     = (const float*)d_in[0];
    const int*   ei    = (const int*)d_in[1];
    const float* W1    = (const float*)d_in[2];
    const float* asrc1 = (const float*)d_in[3];
    const float* adst1 = (const float*)d_in[4];
    const float* b1    = (const float*)d_in[5];
    const float* W2    = (const float*)d_in[6];
    const float* asrc2 = (const float*)d_in[7];
    const float* adst2 = (const float*)d_in[8];
    const float* b2    = (const float*)d_in[9];
    float* out = (float*)d_out;

    int n = in_sizes[0] / 128;   // 30000
    int E = in_sizes[1] / 2;     // 480000

    float *p_h1, *p_act1, *p_h2;
    float4 *p_as, *p_ad;
    cudaGetSymbolAddress((void**)&p_h1,   g_h1);
    cudaGetSymbolAddress((void**)&p_act1, g_act1);
    cudaGetSymbolAddress((void**)&p_h2,   g_h2);
    cudaGetSymbolAddress((void**)&p_as,   g_as);
    cudaGetSymbolAddress((void**)&p_ad,   g_ad);

    const int* e_src = ei;
    const int* e_dst = ei + E;

    static cudaStream_t s_csr = nullptr;
    static cudaEvent_t  ev_fork = nullptr, ev_join = nullptr;
    if (s_csr == nullptr) {
        cudaStreamCreateWithFlags(&s_csr, cudaStreamNonBlocking);
        cudaEventCreateWithFlags(&ev_fork, cudaEventDisableTiming);
        cudaEventCreateWithFlags(&ev_join, cudaEventDisableTiming);
    }

    dim3 ggrid((n + 63) / 64, 2);
    int agg_blocks = (n * 128 + 255) / 256;   // 4 warps per node

    // fork: CSR build on side stream
    cudaEventRecord(ev_fork, 0);
    cudaStreamWaitEvent(s_csr, ev_fork, 0);
    zero_kernel<<<(n + 255) / 256, 256, 0, s_csr>>>(n);
    hist_kernel<<<(E + 1023) / 1024, 256, 0, s_csr>>>(e_dst, E);
    scan_kernel<<<1, 1024, 0, s_csr>>>(n);
    scatter_kernel<<<(E + 1023) / 1024, 256, 0, s_csr>>>(e_src, e_dst, E);
    cudaEventRecord(ev_join, s_csr);

    // main stream: layer 1
    gemm_alpha<<<ggrid, 128>>>(x, W1, p_h1, n, asrc1, adst1, p_as, p_ad);
    cudaStreamWaitEvent(0, ev_join, 0);
    agg1_kernel<<<agg_blocks, 256>>>(p_h1, b1, p_act1, n);

    // layer 2
    gemm_alpha<<<ggrid, 128>>>(p_act1, W2, p_h2, n, asrc2, adst2, p_as, p_ad);
    agg2_kernel<<<agg_blocks, 256>>>(p_h2, b2, out, n);
}

// round 15
// speedup vs baseline: 1.1986x; 1.1986x over previous
#include <cuda_runtime.h>
#include <math.h>

#define N_MAX   32768
#define EMAX    600000
#define FULL_M  0xffffffffu
#define NEG_SLOPE 0.2f
#define EPS_    1e-16f

// ---------------- device scratch (static: no allocation allowed) ----------------
__device__ int   g_counts[N_MAX];
__device__ int   g_rowptr[N_MAX + 1];
__device__ int   g_edge_off[EMAX];
__device__ int   g_csr_src[EMAX];
__device__ __align__(16) float g_h1[N_MAX * 128];
__device__ __align__(16) float g_act1[N_MAX * 128];
__device__ __align__(16) float g_h2[N_MAX * 128];
__device__ float4 g_as[N_MAX];   // per-row alpha_src partials by 32-col chunk
__device__ float4 g_ad[N_MAX];   // per-row alpha_dst partials by 32-col chunk

__device__ __forceinline__ float lrelu(float v) { return v > 0.f ? v : NEG_SLOPE * v; }

// ---------------- CSR construction ----------------
__global__ void zero_kernel(int n) {
    int i = blockIdx.x * blockDim.x + threadIdx.x;
    if (i < n) g_counts[i] = 0;
}

__global__ void hist_kernel(const int* __restrict__ dst, int E) {
    int i = (blockIdx.x * blockDim.x + threadIdx.x) * 4;
    if (i + 3 < E) {
        int4 d = *(const int4*)(dst + i);
        int o0 = atomicAdd(&g_counts[d.x], 1);
        int o1 = atomicAdd(&g_counts[d.y], 1);
        int o2 = atomicAdd(&g_counts[d.z], 1);
        int o3 = atomicAdd(&g_counts[d.w], 1);
        *(int4*)(g_edge_off + i) = make_int4(o0, o1, o2, o3);
    } else {
        for (int j = i; j < E; j++)
            g_edge_off[j] = atomicAdd(&g_counts[dst[j]], 1);
    }
}

__global__ __launch_bounds__(1024) void scan_kernel(int n) {
    __shared__ int wsum[32];
    int tid = threadIdx.x, lane = tid & 31, wid = tid >> 5;
    int base = tid * 32;
    int local[32];
    int sum = 0;
    #pragma unroll
    for (int j = 0; j < 32; j++) {
        int i = base + j;
        local[j] = sum;
        sum += (i < n) ? (g_counts[i] + 1) : 0;   // +1 = self loop
    }
    int x = sum;
    #pragma unroll
    for (int d = 1; d < 32; d <<= 1) {
        int t = __shfl_up_sync(FULL_M, x, d);
        if (lane >= d) x += t;
    }
    if (lane == 31) wsum[wid] = x;
    __syncthreads();
    if (wid == 0) {
        int y = wsum[lane];
        #pragma unroll
        for (int d = 1; d < 32; d <<= 1) {
            int t = __shfl_up_sync(FULL_M, y, d);
            if (lane >= d) y += t;
        }
        wsum[lane] = y;
    }
    __syncthreads();
    int offset = (x - sum) + (wid > 0 ? wsum[wid - 1] : 0);
    if (tid == 0) g_rowptr[0] = 0;
    #pragma unroll
    for (int j = 0; j < 32; j++) {
        int i = base + j;
        if (i < n) {
            int c = g_counts[i];
            int start = offset + local[j];
            g_rowptr[i + 1] = start + c + 1;
            g_csr_src[start] = i;                 // self loop first
        }
    }
}

__global__ void scatter_kernel(const int* __restrict__ src,
                               const int* __restrict__ dst, int E) {
    int i = (blockIdx.x * blockDim.x + threadIdx.x) * 4;
    if (i + 3 < E) {
        int4 s = *(const int4*)(src + i);
        int4 d = *(const int4*)(dst + i);
        int4 o = *(const int4*)(g_edge_off + i);
        g_csr_src[g_rowptr[d.x] + 1 + o.x] = s.x;
        g_csr_src[g_rowptr[d.y] + 1 + o.y] = s.y;
        g_csr_src[g_rowptr[d.z] + 1 + o.z] = s.z;
        g_csr_src[g_rowptr[d.w] + 1 + o.w] = s.w;
    } else {
        for (int j = i; j < E; j++)
            g_csr_src[g_rowptr[dst[j]] + 1 + g_edge_off[j]] = src[j];
    }
}

// ---------------- GEMM + fused alpha (R13, + row0 offset for M-split) ----------------
__global__ __launch_bounds__(128) void gemm_alpha(
    const float* __restrict__ A, const float* __restrict__ B,
    float* __restrict__ C, int row0, int M,
    const float* __restrict__ av, const float* __restrict__ dv,
    float4* __restrict__ as_out, float4* __restrict__ ad_out)
{
    __shared__ __align__(16) float As[32][68];   // [k][m]
    __shared__ __align__(16) float Bs[32][68];   // [k][n]
    int tid = threadIdx.x;
    int tx = tid & 15, ty = tid >> 4;
    int m0 = row0 + blockIdx.x * 64, n0 = blockIdx.y * 64;
    float acc[8][4] = {};
    for (int kk = 0; kk < 4; kk++) {
        int k0 = kk * 32;
        #pragma unroll
        for (int t = 0; t < 4; t++) {
            int idx = tid + t * 128;
            int r = idx >> 3, c4 = idx & 7;
            float4 v = make_float4(0.f, 0.f, 0.f, 0.f);
            int row = m0 + r;
            if (row < M) v = *(const float4*)(A + (size_t)row * 128 + k0 + c4 * 4);
            As[c4 * 4 + 0][r] = v.x; As[c4 * 4 + 1][r] = v.y;
            As[c4 * 4 + 2][r] = v.z; As[c4 * 4 + 3][r] = v.w;
        }
        #pragma unroll
        for (int t = 0; t < 4; t++) {
            int idx = tid + t * 128;
            int k = idx >> 4, c4 = idx & 15;
            float4 v = *(const float4*)(B + (k0 + k) * 128 + n0 + c4 * 4);
            *(float4*)&Bs[k][c4 * 4] = v;
        }
        __syncthreads();
        #pragma unroll
        for (int k = 0; k < 32; k++) {
            float a[8], b[4];
            *(float4*)&a[0] = *(const float4*)&As[k][ty * 8];
            *(float4*)&a[4] = *(const float4*)&As[k][ty * 8 + 4];
            *(float4*)&b[0] = *(const float4*)&Bs[k][tx * 4];
            #pragma unroll
            for (int i = 0; i < 8; i++)
                #pragma unroll
                for (int j = 0; j < 4; j++)
                    acc[i][j] += a[i] * b[j];
        }
        __syncthreads();
    }
    #pragma unroll
    for (int i = 0; i < 8; i++) {
        int row = m0 + ty * 8 + i;
        if (row < M)
            *(float4*)(C + (size_t)row * 128 + n0 + tx * 4) =
                make_float4(acc[i][0], acc[i][1], acc[i][2], acc[i][3]);
    }
    float a0 = av[n0 + tx * 4], a1 = av[n0 + tx * 4 + 1],
          a2 = av[n0 + tx * 4 + 2], a3 = av[n0 + tx * 4 + 3];
    float d0 = dv[n0 + tx * 4], d1 = dv[n0 + tx * 4 + 1],
          d2 = dv[n0 + tx * 4 + 2], d3 = dv[n0 + tx * 4 + 3];
    int comp = (n0 >> 5) + (tx >> 3);
    #pragma unroll
    for (int i = 0; i < 8; i++) {
        float s = acc[i][0] * a0 + acc[i][1] * a1 + acc[i][2] * a2 + acc[i][3] * a3;
        float d = acc[i][0] * d0 + acc[i][1] * d1 + acc[i][2] * d2 + acc[i][3] * d3;
        s += __shfl_xor_sync(FULL_M, s, 1); d += __shfl_xor_sync(FULL_M, d, 1);
        s += __shfl_xor_sync(FULL_M, s, 2); d += __shfl_xor_sync(FULL_M, d, 2);
        s += __shfl_xor_sync(FULL_M, s, 4); d += __shfl_xor_sync(FULL_M, d, 4);
        int row = m0 + ty * 8 + i;
        if ((tx & 7) == 0 && row < M) {
            ((float*)&as_out[row])[comp] = s;
            ((float*)&ad_out[row])[comp] = d;
        }
    }
}

// ---------------- layer-1 aggregation (R13 shape, occupancy-capped, node range) ---
__global__ __launch_bounds__(256, 4) void agg1_kernel(
    const float* __restrict__ h, const float* __restrict__ b1,
    float* __restrict__ out, int wbeg, int wend) {
    int w = wbeg + ((blockIdx.x * blockDim.x + threadIdx.x) >> 5);
    int lane = threadIdx.x & 31;
    if (w >= wend) return;
    int beg = g_rowptr[w], end = g_rowptr[w + 1];
    float4 ad = g_ad[w];

    float acc0 = 0.f, acc1 = 0.f, acc2 = 0.f, acc3 = 0.f;
    float dn0 = 0.f, dn1 = 0.f, dn2 = 0.f, dn3 = 0.f;
    for (int g = beg; g < end; g += 32) {
        int i = g + lane;
        float e0 = 0.f, e1 = 0.f, e2 = 0.f, e3 = 0.f;
        int s = 0;
        if (i < end) {
            s = g_csr_src[i];
            float4 a = g_as[s];
            e0 = __expf(lrelu(a.x + ad.x));
            e1 = __expf(lrelu(a.y + ad.y));
            e2 = __expf(lrelu(a.z + ad.z));
            e3 = __expf(lrelu(a.w + ad.w));
        }
        dn0 += e0; dn1 += e1; dn2 += e2; dn3 += e3;
        #pragma unroll
        for (int j = 0; j < 32; j++) {
            float f0 = __shfl_sync(FULL_M, e0, j);
            float f1 = __shfl_sync(FULL_M, e1, j);
            float f2 = __shfl_sync(FULL_M, e2, j);
            float f3 = __shfl_sync(FULL_M, e3, j);
            int  sj = __shfl_sync(FULL_M, s, j);
            if (f0 + f1 + f2 + f3 > 0.f) {
                const float* hp = h + (size_t)sj * 128;
                acc0 += f0 * hp[lane];
                acc1 += f1 * hp[lane + 32];
                acc2 += f2 * hp[lane + 64];
                acc3 += f3 * hp[lane + 96];
            }
        }
    }
    #pragma unroll
    for (int o = 16; o; o >>= 1) {
        dn0 += __shfl_xor_sync(FULL_M, dn0, o);
        dn1 += __shfl_xor_sync(FULL_M, dn1, o);
        dn2 += __shfl_xor_sync(FULL_M, dn2, o);
        dn3 += __shfl_xor_sync(FULL_M, dn3, o);
    }
    float v0 = acc0 / (dn0 + EPS_) + b1[lane];
    float v1 = acc1 / (dn1 + EPS_) + b1[lane + 32];
    float v2 = acc2 / (dn2 + EPS_) + b1[lane + 64];
    float v3 = acc3 / (dn3 + EPS_) + b1[lane + 96];
    float* op = out + (size_t)w * 128;
    op[lane]      = v0 > 0.f ? v0 : expm1f(v0);   // ELU(alpha=1)
    op[lane + 32] = v1 > 0.f ? v1 : expm1f(v1);
    op[lane + 64] = v2 > 0.f ? v2 : expm1f(v2);
    op[lane + 96] = v3 > 0.f ? v3 : expm1f(v3);
}

// ---------------- layer-2 aggregation (R13 shape, occupancy-capped) ----------------
__global__ __launch_bounds__(256, 4) void agg2_kernel(
    const float* __restrict__ h, const float* __restrict__ b2,
    float* __restrict__ out, int n) {
    int w = (blockIdx.x * blockDim.x + threadIdx.x) >> 5;
    int lane = threadIdx.x & 31;
    if (w >= n) return;
    int beg = g_rowptr[w], end = g_rowptr[w + 1];
    float4 adv = g_ad[w];
    float adn = (adv.x + adv.y) + (adv.z + adv.w);

    float acc0 = 0.f, acc1 = 0.f, acc2 = 0.f, acc3 = 0.f, dn = 0.f;
    for (int g = beg; g < end; g += 32) {
        int i = g + lane;
        float e = 0.f; int s = 0;
        if (i < end) {
            s = g_csr_src[i];
            float4 a = g_as[s];
            e = __expf(lrelu((a.x + a.y) + (a.z + a.w) + adn));
        }
        dn += e;
        #pragma unroll
        for (int j = 0; j < 32; j++) {
            float f = __shfl_sync(FULL_M, e, j);
            int  sj = __shfl_sync(FULL_M, s, j);
            if (f > 0.f) {
                const float* hp = h + (size_t)sj * 128;
                acc0 += f * hp[lane];
                acc1 += f * hp[lane + 32];
                acc2 += f * hp[lane + 64];
                acc3 += f * hp[lane + 96];
            }
        }
    }
    #pragma unroll
    for (int o = 16; o; o >>= 1)
        dn += __shfl_xor_sync(FULL_M, dn, o);
    float inv = 1.f / (dn + EPS_);
    float* op = out + (size_t)w * 128;
    op[lane]      = acc0 * inv + b2[lane];
    op[lane + 32] = acc1 * inv + b2[lane + 32];
    op[lane + 64] = acc2 * inv + b2[lane + 64];
    op[lane + 96] = acc3 * inv + b2[lane + 96];
}

// ---------------- launch: CSR ∥ gemm1; agg1/gemm2 pipelined by node-half ----------
extern "C" void kernel_launch(void* const* d_in, const int* in_sizes, int n_in,
                              void* d_out, int out_size) {
    const float* x     = (const float*)d_in[0];
    const int*   ei    = (const int*)d_in[1];
    const float* W1    = (const float*)d_in[2];
    const float* asrc1 = (const float*)d_in[3];
    const float* adst1 = (const float*)d_in[4];
    const float* b1    = (const float*)d_in[5];
    const float* W2    = (const float*)d_in[6];
    const float* asrc2 = (const float*)d_in[7];
    const float* adst2 = (const float*)d_in[8];
    const float* b2    = (const float*)d_in[9];
    float* out = (float*)d_out;

    int n = in_sizes[0] / 128;   // 30000
    int E = in_sizes[1] / 2;     // 480000
    int n2 = (n / 2 + 63) & ~63; // half point, 64-aligned (15040)

    float *p_h1, *p_act1, *p_h2;
    float4 *p_as, *p_ad;
    cudaGetSymbolAddress((void**)&p_h1,   g_h1);
    cudaGetSymbolAddress((void**)&p_act1, g_act1);
    cudaGetSymbolAddress((void**)&p_h2,   g_h2);
    cudaGetSymbolAddress((void**)&p_as,   g_as);
    cudaGetSymbolAddress((void**)&p_ad,   g_ad);

    const int* e_src = ei;
    const int* e_dst = ei + E;

    static cudaStream_t s_side = nullptr;
    static cudaEvent_t  ev_fork = nullptr, ev_join = nullptr,
                        ev_a1lo = nullptr, ev_g2lo = nullptr;
    if (s_side == nullptr) {
        cudaStreamCreateWithFlags(&s_side, cudaStreamNonBlocking);
        cudaEventCreateWithFlags(&ev_fork, cudaEventDisableTiming);
        cudaEventCreateWithFlags(&ev_join, cudaEventDisableTiming);
        cudaEventCreateWithFlags(&ev_a1lo, cudaEventDisableTiming);
        cudaEventCreateWithFlags(&ev_g2lo, cudaEventDisableTiming);
    }

    // fork: CSR build on side stream
    cudaEventRecord(ev_fork, 0);
    cudaStreamWaitEvent(s_side, ev_fork, 0);
    zero_kernel<<<(n + 255) / 256, 256, 0, s_side>>>(n);
    hist_kernel<<<(E + 1023) / 1024, 256, 0, s_side>>>(e_dst, E);
    scan_kernel<<<1, 1024, 0, s_side>>>(n);
    scatter_kernel<<<(E + 1023) / 1024, 256, 0, s_side>>>(e_src, e_dst, E);
    cudaEventRecord(ev_join, s_side);

    // main: gemm1 (full), then pipelined agg1/gemm2
    dim3 g1grid((n + 63) / 64, 2);
    gemm_alpha<<<g1grid, 128>>>(x, W1, p_h1, 0, n, asrc1, adst1, p_as, p_ad);
    cudaStreamWaitEvent(0, ev_join, 0);

    int wb_lo = (n2 * 32 + 255) / 256;
    int wb_hi = ((n - n2) * 32 + 255) / 256;
    agg1_kernel<<<wb_lo, 256>>>(p_h1, b1, p_act1, 0, n2);       // launch #6 -> ncu
    cudaEventRecord(ev_a1lo, 0);

    // side: gemm2 on rows [0, n2) overlapping agg1_hi
    cudaStreamWaitEvent(s_side, ev_a1lo, 0);
    dim3 g2lo(n2 / 64, 2);
    gemm_alpha<<<g2lo, 128, 0, s_side>>>(p_act1, W2, p_h2, 0, n2,
                                         asrc2, adst2, p_as, p_ad);
    cudaEventRecord(ev_g2lo, s_side);

    // main: agg1 second half, then gemm2 on remaining rows
    agg1_kernel<<<wb_hi, 256>>>(p_h1, b1, p_act1, n2, n);
    dim3 g2hi((n - n2 + 63) / 64, 2);
    gemm_alpha<<<g2hi, 128>>>(p_act1, W2, p_h2, n2, n, asrc2, adst2, p_as, p_ad);
    cudaStreamWaitEvent(0, ev_g2lo, 0);

    // agg2 (full)
    int wb_full = (n * 32 + 255) / 256;
    agg2_kernel<<<wb_full, 256>>>(p_h2, b2, out, n);
}